// round 5
// baseline (speedup 1.0000x reference)
#include <cuda_runtime.h>
#include <math.h>

#define BSZ    128
#define MAXLEN 256
#define DCHAR  256
#define DHID   1024
#define VOC    512
#define BT     (BSZ * MAXLEN)   // 32768
#define BH     (BSZ * DHID)     // 131072

// ---------------------------------------------------------------------------
// Scratch (allocation-free: __device__ globals)
// ---------------------------------------------------------------------------
__device__ float g_xp_enc[BT * DHID];
__device__ float g_xp_dec[BT * DHID];
__device__ float g_states[BT * DHID];
__device__ float g_hT0[DHID * BSZ];     // transposed hidden ping [k][b]
__device__ float g_hT1[DHID * BSZ];     // transposed hidden pong [k][b]

__device__ unsigned g_bar_cnt   = 0;
__device__ unsigned g_bar_phase = 0;

// ---------------------------------------------------------------------------
// Generic tiled SGEMM with row gather (unchanged):
//   C[row, n] = sum_k A[src(row), k] * B[n, k] + bias1[n] (+ bias2[n])
// ---------------------------------------------------------------------------
#define GBM 64
#define GBN 64
#define GBK 16

__global__ void gemm_gather_kernel(const float* __restrict__ A, int lda,
                                   const int* __restrict__ tokens, int gmode, int T,
                                   const float* __restrict__ B,
                                   const float* __restrict__ bias1,
                                   const float* __restrict__ bias2,
                                   float* __restrict__ C,
                                   int N, int K)
{
    __shared__ __align__(16) float As[GBK][GBM + 4];
    __shared__ __align__(16) float Bs[GBK][GBN + 4];
    __shared__ int rowsrc[GBM];

    const int bm  = blockIdx.y * GBM;
    const int bn  = blockIdx.x * GBN;
    const int tid = threadIdx.x;

    if (tid < GBM) {
        int row = bm + tid;
        int src = row;
        if (gmode == 1) {
            src = tokens[row];
        } else if (gmode == 2) {
            int t = row % T;
            src = (t == 0) ? -1 : tokens[row - 1];
        }
        rowsrc[tid] = src;
    }
    __syncthreads();

    const int tm = (tid >> 4) * 4;
    const int tn = (tid & 15) * 4;

    float acc[4][4] = {};

    for (int k0 = 0; k0 < K; k0 += GBK) {
        #pragma unroll
        for (int i = 0; i < 4; i++) {
            int idx = tid + i * 256;
            int m = idx >> 4, kk = idx & 15;
            int src = rowsrc[m];
            As[kk][m] = (src < 0) ? 0.0f : A[src * lda + k0 + kk];
        }
        #pragma unroll
        for (int i = 0; i < 4; i++) {
            int idx = tid + i * 256;
            int n = idx >> 4, kk = idx & 15;
            Bs[kk][n] = B[(bn + n) * K + k0 + kk];
        }
        __syncthreads();

        #pragma unroll
        for (int kk = 0; kk < GBK; kk++) {
            float4 a = *reinterpret_cast<const float4*>(&As[kk][tm]);
            float4 b = *reinterpret_cast<const float4*>(&Bs[kk][tn]);
            acc[0][0] += a.x * b.x; acc[0][1] += a.x * b.y; acc[0][2] += a.x * b.z; acc[0][3] += a.x * b.w;
            acc[1][0] += a.y * b.x; acc[1][1] += a.y * b.y; acc[1][2] += a.y * b.z; acc[1][3] += a.y * b.w;
            acc[2][0] += a.z * b.x; acc[2][1] += a.z * b.y; acc[2][2] += a.z * b.z; acc[2][3] += a.z * b.w;
            acc[3][0] += a.w * b.x; acc[3][1] += a.w * b.y; acc[3][2] += a.w * b.z; acc[3][3] += a.w * b.w;
        }
        __syncthreads();
    }

    #pragma unroll
    for (int j = 0; j < 4; j++) {
        int n = bn + tn + j;
        float bb = (bias1 ? bias1[n] : 0.0f) + (bias2 ? bias2[n] : 0.0f);
        #pragma unroll
        for (int i = 0; i < 4; i++) {
            C[(bm + tm + i) * N + n] = acc[i][j] + bb;
        }
    }
}

// ---------------------------------------------------------------------------
// Persistent recurrence kernel, v2.
// 128 CTAs (1/SM), 256 threads (8 warps = 2/SMSP).
// Split-k: warp-group 0 (warps 0-3) does k in [0,512), group 1 does [512,1024),
// followed by an smem partial-sum reduction.
// Whh slice [32n x 1024k] resident in smem (Ws[k][n], stride 34).
// h is staged per 64-k chunk into smem PRE-DUPLICATED ({h,h} pairs) so the
// inner loop needs zero pack MOVs: 2x LDS.128 + 1x LDS.64 + 4x FFMA2 per 8 MAC.
// ---------------------------------------------------------------------------
#define NCTA      128
#define WS_STRIDE 34
#define WS_F      (DHID * WS_STRIDE)        // 34816 floats
#define KC        64                        // k-chunk per stage
#define CHUNK_F   (KC * 64)                 // 4096 floats (dup: 64 floats per k)
#define SMEM_BYTES ((WS_F + 4 * CHUNK_F) * 4)   // 204800 B

__device__ __forceinline__ void load_whh_slice(float* Ws, const float* __restrict__ W,
                                               int ntile, int tid)
{
    for (int idx = tid; idx < 32 * 256; idx += 256) {
        int row = idx >> 8;          // 0..31 (n local)
        int c4  = idx & 255;         // 0..255 (k/4)
        float4 v = *reinterpret_cast<const float4*>(&W[(ntile + row) * DHID + c4 * 4]);
        int k = c4 * 4;
        Ws[(k + 0) * WS_STRIDE + row] = v.x;
        Ws[(k + 1) * WS_STRIDE + row] = v.y;
        Ws[(k + 2) * WS_STRIDE + row] = v.z;
        Ws[(k + 3) * WS_STRIDE + row] = v.w;
    }
}

__device__ __forceinline__ void grid_barrier(unsigned target)
{
    __syncthreads();
    if (threadIdx.x == 0) {
        __threadfence();
        unsigned arrived = atomicAdd(&g_bar_cnt, 1u);
        if (arrived == NCTA - 1) {
            atomicExch(&g_bar_cnt, 0u);
            __threadfence();
            atomicAdd(&g_bar_phase, 1u);
        } else {
            volatile unsigned* vp = &g_bar_phase;
            while ((int)(*vp - target) < 0)
                __nanosleep(32);
            __threadfence();
        }
    }
    __syncthreads();
}

__device__ __forceinline__ float2 u64_to_f2(unsigned long long v)
{
    float2 f;
    asm("mov.b64 {%0,%1},%2;" : "=f"(f.x), "=f"(f.y) : "l"(v));
    return f;
}

__global__ void __launch_bounds__(256, 1)
rnn_persistent_kernel(const float* __restrict__ xp_enc,
                      const float* __restrict__ xp_dec,
                      const float* __restrict__ enc_Whh,
                      const float* __restrict__ dec_Whh,
                      float* __restrict__ states,
                      float* __restrict__ hT0,
                      float* __restrict__ hT1)
{
    extern __shared__ float sm[];
    float* Ws = sm;                  // [1024][34]
    float* hd = sm + WS_F;           // 4 dup buffers of CHUNK_F floats

    const int tid = threadIdx.x;
    const int ni = blockIdx.x, mi = blockIdx.y;
    const int btile = mi * 32, ntile = ni * 32;

    const int grp = tid >> 7;            // k-group 0/1
    const int gt  = tid & 127;
    const int wg  = gt >> 5;             // warp within group
    const int l   = gt & 31;
    const int bq  = (wg & 1) * 4 + (l & 3);        // 0..7 (b quad)
    const int np  = (wg >> 1) * 8 + (l >> 2);      // 0..15 (n pair)
    const int b_local = bq * 4;
    const int n_local = np * 2;
    const int kgbase  = grp * 512;

    float* hb0 = hd + grp * 2 * CHUNK_F;  // this group's double buffer

    __shared__ unsigned s_ph;
    if (tid == 0) s_ph = *(volatile unsigned*)&g_bar_phase;

    // Zero h0 (ping buffer): 128 CTAs x 256 threads x 4 floats = 131072.
    {
        const int cta = mi * 32 + ni;
        *reinterpret_cast<float4*>(&hT0[(cta * 256 + tid) * 4]) =
            make_float4(0.f, 0.f, 0.f, 0.f);
    }

    load_whh_slice(Ws, enc_Whh, ntile, tid);
    __syncthreads();
    unsigned target = s_ph + 1;
    grid_barrier(target);

    for (int s = 0; s < 512; s++) {
        if (s == 256) {
            load_whh_slice(Ws, dec_Whh, ntile, tid);
            __syncthreads();
        }
        const float* __restrict__ hin  = (s & 1) ? hT1 : hT0;
        float* __restrict__       hout = (s & 1) ? hT0 : hT1;
        const int t = s & 255;
        const float* __restrict__ xp = (s < 256) ? xp_enc : xp_dec;

        // Prefetch xp for the epilogue (independent of h -> overlaps the GEMM).
        float2 xr[4];
        if (grp == 0) {
            #pragma unroll
            for (int p = 0; p < 4; p++)
                xr[p] = *reinterpret_cast<const float2*>(
                    &xp[((size_t)(btile + b_local + p) * MAXLEN + t) * DHID + ntile + n_local]);
        }

        // Stage chunk 0 of this group's k-range (duplicated).
        float4 r[4];
        #pragma unroll
        for (int i = 0; i < 4; i++) {
            int slot = gt + i * 128;
            int k = slot >> 3, bqs = slot & 7;
            r[i] = *reinterpret_cast<const float4*>(
                &hin[(kgbase + k) * BSZ + btile + bqs * 4]);
        }
        #pragma unroll
        for (int i = 0; i < 4; i++) {
            int slot = gt + i * 128;
            int k = slot >> 3, bqs = slot & 7;
            float* d = hb0 + k * 64 + bqs * 8;
            reinterpret_cast<float4*>(d)[0] = make_float4(r[i].x, r[i].x, r[i].y, r[i].y);
            reinterpret_cast<float4*>(d)[1] = make_float4(r[i].z, r[i].z, r[i].w, r[i].w);
        }
        __syncthreads();

        unsigned long long acc0 = 0ull, acc1 = 0ull, acc2 = 0ull, acc3 = 0ull;

        #pragma unroll 1
        for (int c = 0; c < 8; c++) {
            const int cb = c & 1;
            if (c < 7) {
                #pragma unroll
                for (int i = 0; i < 4; i++) {
                    int slot = gt + i * 128;
                    int k = slot >> 3, bqs = slot & 7;
                    r[i] = *reinterpret_cast<const float4*>(
                        &hin[(kgbase + (c + 1) * KC + k) * BSZ + btile + bqs * 4]);
                }
            }
            const float* hp = hb0 + cb * CHUNK_F + bq * 8;
            const float* wp = Ws + (kgbase + c * KC) * WS_STRIDE + n_local;
            #pragma unroll 16
            for (int kk = 0; kk < KC; kk++) {
                ulonglong2 hA = *reinterpret_cast<const ulonglong2*>(hp + kk * 64);
                ulonglong2 hB = *reinterpret_cast<const ulonglong2*>(hp + kk * 64 + 4);
                unsigned long long wv =
                    *reinterpret_cast<const unsigned long long*>(wp + kk * WS_STRIDE);
                asm("fma.rn.f32x2 %0,%1,%2,%0;" : "+l"(acc0) : "l"(hA.x), "l"(wv));
                asm("fma.rn.f32x2 %0,%1,%2,%0;" : "+l"(acc1) : "l"(hA.y), "l"(wv));
                asm("fma.rn.f32x2 %0,%1,%2,%0;" : "+l"(acc2) : "l"(hB.x), "l"(wv));
                asm("fma.rn.f32x2 %0,%1,%2,%0;" : "+l"(acc3) : "l"(hB.y), "l"(wv));
            }
            if (c < 7) {
                #pragma unroll
                for (int i = 0; i < 4; i++) {
                    int slot = gt + i * 128;
                    int k = slot >> 3, bqs = slot & 7;
                    float* d = hb0 + (1 - cb) * CHUNK_F + k * 64 + bqs * 8;
                    reinterpret_cast<float4*>(d)[0] = make_float4(r[i].x, r[i].x, r[i].y, r[i].y);
                    reinterpret_cast<float4*>(d)[1] = make_float4(r[i].z, r[i].z, r[i].w, r[i].w);
                }
                __syncthreads();
            }
        }

        // Split-k reduction: group 1 stores partials into its (now idle) buffer 0.
        unsigned long long* red = reinterpret_cast<unsigned long long*>(hd + 2 * CHUNK_F);
        if (grp == 1) {
            red[gt * 4 + 0] = acc0;
            red[gt * 4 + 1] = acc1;
            red[gt * 4 + 2] = acc2;
            red[gt * 4 + 3] = acc3;
        }
        __syncthreads();

        if (grp == 0) {
            unsigned long long p0 = red[gt * 4 + 0], p1 = red[gt * 4 + 1];
            unsigned long long p2 = red[gt * 4 + 2], p3 = red[gt * 4 + 3];
            asm("add.rn.f32x2 %0,%0,%1;" : "+l"(acc0) : "l"(p0));
            asm("add.rn.f32x2 %0,%0,%1;" : "+l"(acc1) : "l"(p1));
            asm("add.rn.f32x2 %0,%0,%1;" : "+l"(acc2) : "l"(p2));
            asm("add.rn.f32x2 %0,%0,%1;" : "+l"(acc3) : "l"(p3));

            float2 a0 = u64_to_f2(acc0), a1 = u64_to_f2(acc1);
            float2 a2 = u64_to_f2(acc2), a3 = u64_to_f2(acc3);
            float2 th[4];
            th[0] = make_float2(tanhf(a0.x + xr[0].x), tanhf(a0.y + xr[0].y));
            th[1] = make_float2(tanhf(a1.x + xr[1].x), tanhf(a1.y + xr[1].y));
            th[2] = make_float2(tanhf(a2.x + xr[2].x), tanhf(a2.y + xr[2].y));
            th[3] = make_float2(tanhf(a3.x + xr[3].x), tanhf(a3.y + xr[3].y));

            const int ng = ntile + n_local;
            *reinterpret_cast<float4*>(&hout[ng * BSZ + btile + b_local]) =
                make_float4(th[0].x, th[1].x, th[2].x, th[3].x);
            *reinterpret_cast<float4*>(&hout[(ng + 1) * BSZ + btile + b_local]) =
                make_float4(th[0].y, th[1].y, th[2].y, th[3].y);

            if (s >= 256) {
                #pragma unroll
                for (int p = 0; p < 4; p++)
                    *reinterpret_cast<float2*>(
                        &states[((size_t)(btile + b_local + p) * MAXLEN + t) * DHID + ng]) = th[p];
            }
        }

        target++;
        grid_barrier(target);
    }
}

// ---------------------------------------------------------------------------
// In-place row-wise log-softmax over VOC=512 columns. One warp per row.
// ---------------------------------------------------------------------------
__global__ void log_softmax_kernel(float* __restrict__ data)
{
    int gw   = (blockIdx.x * blockDim.x + threadIdx.x) >> 5;
    int lane = threadIdx.x & 31;
    if (gw >= BT) return;
    float* row = data + (size_t)gw * VOC;

    float v[16];
    float mx = -1e30f;
    #pragma unroll
    for (int i = 0; i < 16; i++) {
        v[i] = row[lane + i * 32];
        mx = fmaxf(mx, v[i]);
    }
    #pragma unroll
    for (int o = 16; o > 0; o >>= 1)
        mx = fmaxf(mx, __shfl_xor_sync(0xffffffffu, mx, o));

    float s = 0.0f;
    #pragma unroll
    for (int i = 0; i < 16; i++) s += expf(v[i] - mx);
    #pragma unroll
    for (int o = 16; o > 0; o >>= 1)
        s += __shfl_xor_sync(0xffffffffu, s, o);

    float lse = mx + logf(s);
    #pragma unroll
    for (int i = 0; i < 16; i++) row[lane + i * 32] = v[i] - lse;
}

// ---------------------------------------------------------------------------
extern "C" void kernel_launch(void* const* d_in, const int* in_sizes, int n_in,
                              void* d_out, int out_size)
{
    const int*   inputs  = (const int*)d_in[0];
    const int*   outputs = (const int*)d_in[1];
    const float* emb     = (const float*)d_in[2];
    const float* enc_Wih = (const float*)d_in[3];
    const float* enc_Whh = (const float*)d_in[4];
    const float* enc_bih = (const float*)d_in[5];
    const float* enc_bhh = (const float*)d_in[6];
    const float* dec_Wih = (const float*)d_in[7];
    const float* dec_Whh = (const float*)d_in[8];
    const float* dec_bih = (const float*)d_in[9];
    const float* dec_bhh = (const float*)d_in[10];
    const float* out_W   = (const float*)d_in[11];
    const float* out_b   = (const float*)d_in[12];
    float* out = (float*)d_out;

    float *xp_enc, *xp_dec, *states, *hT0, *hT1;
    cudaGetSymbolAddress((void**)&xp_enc, g_xp_enc);
    cudaGetSymbolAddress((void**)&xp_dec, g_xp_dec);
    cudaGetSymbolAddress((void**)&states, g_states);
    cudaGetSymbolAddress((void**)&hT0,    g_hT0);
    cudaGetSymbolAddress((void**)&hT1,    g_hT1);

    // Input projections (embedding gather fused): xp = emb[tok] @ Wih^T + bih + bhh
    gemm_gather_kernel<<<dim3(DHID / GBN, BT / GBM), 256>>>(
        emb, DCHAR, inputs, 1, MAXLEN, enc_Wih, enc_bih, enc_bhh, xp_enc, DHID, DCHAR);
    gemm_gather_kernel<<<dim3(DHID / GBN, BT / GBM), 256>>>(
        emb, DCHAR, outputs, 2, MAXLEN, dec_Wih, dec_bih, dec_bhh, xp_dec, DHID, DCHAR);

    // Persistent recurrence: encoder 256 steps + decoder 256 steps, grid-synced.
    cudaFuncSetAttribute(rnn_persistent_kernel,
                         cudaFuncAttributeMaxDynamicSharedMemorySize, SMEM_BYTES);
    rnn_persistent_kernel<<<dim3(32, 4), 256, SMEM_BYTES>>>(
        xp_enc, xp_dec, enc_Whh, dec_Whh, states, hT0, hT1);

    // logits = states @ out_W^T + out_b -> d_out, then log-softmax in place.
    gemm_gather_kernel<<<dim3(VOC / GBN, BT / GBM), 256>>>(
        states, DHID, nullptr, 0, MAXLEN, out_W, out_b, nullptr, out, VOC, DHID);

    log_softmax_kernel<<<BT / 8, 256>>>(out);
}

// round 6
// speedup vs baseline: 1.3278x; 1.3278x over previous
#include <cuda_runtime.h>
#include <math.h>

#define BSZ    128
#define MAXLEN 256
#define DCHAR  256
#define DHID   1024
#define VOC    512
#define BT     (BSZ * MAXLEN)   // 32768
#define BH     (BSZ * DHID)     // 131072

// ---------------------------------------------------------------------------
// Scratch (allocation-free: __device__ globals)
// ---------------------------------------------------------------------------
__device__ float g_xp_enc[BT * DHID];
__device__ float g_xp_dec[BT * DHID];
__device__ float g_states[BT * DHID];
__device__ float g_hT0[DHID * BSZ];     // transposed hidden ping [k][b]
__device__ float g_hT1[DHID * BSZ];     // transposed hidden pong [k][b]

__device__ unsigned g_bar_cnt   = 0;
__device__ unsigned g_bar_phase = 0;

// ---------------------------------------------------------------------------
// f32x2 helpers
// ---------------------------------------------------------------------------
__device__ __forceinline__ unsigned long long dupf(float x)
{
    unsigned long long r;
    asm("mov.b64 %0,{%1,%1};" : "=l"(r) : "f"(x));
    return r;
}
__device__ __forceinline__ void ffma2(unsigned long long& a,
                                      unsigned long long x, unsigned long long y)
{
    asm("fma.rn.f32x2 %0,%1,%2,%0;" : "+l"(a) : "l"(x), "l"(y));
}
__device__ __forceinline__ void add2(unsigned long long& a, unsigned long long x)
{
    asm("add.rn.f32x2 %0,%0,%1;" : "+l"(a) : "l"(x));
}
__device__ __forceinline__ float2 u64_to_f2(unsigned long long v)
{
    float2 f;
    asm("mov.b64 {%0,%1},%2;" : "=f"(f.x), "=f"(f.y) : "l"(v));
    return f;
}

// ---------------------------------------------------------------------------
// Tiled SGEMM with row gather, FFMA2 inner product.
//   C[row, n] = sum_k A[src(row), k] * B[n, k] + bias1[n] (+ bias2[n])
// B staged in smem DUPLICATED ({b,b} pairs) so FFMA2 needs no pack MOVs:
// per k per thread: 2 LDS.64 (a-pairs) + 2 LDS.128 (b-dups) + 8 FFMA2.
// ---------------------------------------------------------------------------
#define GBM 64
#define GBN 64
#define GBK 16
#define BSD_STRIDE 132    // 2*GBN + 4 pad, *4B = 528 = 33*16 (16B aligned rows)

__global__ void gemm_gather_kernel(const float* __restrict__ A, int lda,
                                   const int* __restrict__ tokens, int gmode, int T,
                                   const float* __restrict__ B,
                                   const float* __restrict__ bias1,
                                   const float* __restrict__ bias2,
                                   float* __restrict__ C,
                                   int N, int K)
{
    __shared__ __align__(16) float As[GBK][GBM + 4];
    __shared__ __align__(16) float Bsd[GBK][BSD_STRIDE];
    __shared__ int rowsrc[GBM];

    const int bm  = blockIdx.y * GBM;
    const int bn  = blockIdx.x * GBN;
    const int tid = threadIdx.x;

    if (tid < GBM) {
        int row = bm + tid;
        int src = row;
        if (gmode == 1) {
            src = tokens[row];
        } else if (gmode == 2) {
            int t = row % T;
            src = (t == 0) ? -1 : tokens[row - 1];
        }
        rowsrc[tid] = src;
    }
    __syncthreads();

    const int tm = (tid >> 4) * 4;
    const int tn = (tid & 15) * 4;

    unsigned long long acc2[2][4] = {};

    for (int k0 = 0; k0 < K; k0 += GBK) {
        #pragma unroll
        for (int i = 0; i < 4; i++) {
            int idx = tid + i * 256;
            int m = idx >> 4, kk = idx & 15;
            int src = rowsrc[m];
            As[kk][m] = (src < 0) ? 0.0f : A[src * lda + k0 + kk];
        }
        #pragma unroll
        for (int i = 0; i < 4; i++) {
            int idx = tid + i * 256;
            int n = idx >> 4, kk = idx & 15;
            float v = B[(bn + n) * K + k0 + kk];
            *reinterpret_cast<unsigned long long*>(&Bsd[kk][2 * n]) = dupf(v);
        }
        __syncthreads();

        #pragma unroll
        for (int kk = 0; kk < GBK; kk++) {
            unsigned long long a01 =
                *reinterpret_cast<const unsigned long long*>(&As[kk][tm]);
            unsigned long long a23 =
                *reinterpret_cast<const unsigned long long*>(&As[kk][tm + 2]);
            ulonglong2 b01 = *reinterpret_cast<const ulonglong2*>(&Bsd[kk][tn * 2]);
            ulonglong2 b23 = *reinterpret_cast<const ulonglong2*>(&Bsd[kk][tn * 2 + 4]);
            ffma2(acc2[0][0], a01, b01.x);
            ffma2(acc2[0][1], a01, b01.y);
            ffma2(acc2[0][2], a01, b23.x);
            ffma2(acc2[0][3], a01, b23.y);
            ffma2(acc2[1][0], a23, b01.x);
            ffma2(acc2[1][1], a23, b01.y);
            ffma2(acc2[1][2], a23, b23.x);
            ffma2(acc2[1][3], a23, b23.y);
        }
        __syncthreads();
    }

    #pragma unroll
    for (int j = 0; j < 4; j++) {
        int n = bn + tn + j;
        float bb = (bias1 ? bias1[n] : 0.0f) + (bias2 ? bias2[n] : 0.0f);
        float2 p0 = u64_to_f2(acc2[0][j]);
        float2 p1 = u64_to_f2(acc2[1][j]);
        C[(bm + tm + 0) * N + n] = p0.x + bb;
        C[(bm + tm + 1) * N + n] = p0.y + bb;
        C[(bm + tm + 2) * N + n] = p1.x + bb;
        C[(bm + tm + 3) * N + n] = p1.y + bb;
    }
}

// ---------------------------------------------------------------------------
// Persistent recurrence kernel, v3.
// 128 CTAs (1/SM), 256 threads (8 warps = 2/SMSP).
// Interleaved split-k: thread group ksg = tid>>6 handles k = 4*i + ksg, so all
// 8 warps consume ONE shared staged chunk (128 k x 32 b, double-buffered).
// Whh slice resident in smem Ws[k][n] (stride 36, 16B-aligned rows).
// Per k per thread (4b x 4n tile): 1 LDS.128 (h) + 1 LDS.128 (w) + 4 MOV dup
// + 8 FFMA2 = 14 instr / 16 MAC -> FFMA2-pipe-bound (8192 cyc/step/SMSP).
// 4-way split-k reduced through smem; ksg0 threads do tanh+xp epilogue.
// ---------------------------------------------------------------------------
#define NCTA      128
#define WS_STRIDE 36
#define WS_F      (DHID * WS_STRIDE)    // 36864 floats (144 KB)
#define KC        128                   // staged k-chunk
#define CHUNK_F   (KC * 32)             // 4096 floats (16 KB)
#define SMEM_BYTES ((WS_F + 2 * CHUNK_F) * 4)   // 180224 B

__device__ __forceinline__ void load_whh_slice(float* Ws, const float* __restrict__ W,
                                               int ntile, int tid)
{
    for (int idx = tid; idx < 32 * 256; idx += 256) {
        int row = idx >> 8;          // 0..31 (n local)
        int c4  = idx & 255;         // 0..255 (k/4)
        float4 v = *reinterpret_cast<const float4*>(&W[(ntile + row) * DHID + c4 * 4]);
        int k = c4 * 4;
        Ws[(k + 0) * WS_STRIDE + row] = v.x;
        Ws[(k + 1) * WS_STRIDE + row] = v.y;
        Ws[(k + 2) * WS_STRIDE + row] = v.z;
        Ws[(k + 3) * WS_STRIDE + row] = v.w;
    }
}

__device__ __forceinline__ void grid_barrier(unsigned target)
{
    __syncthreads();
    if (threadIdx.x == 0) {
        __threadfence();
        unsigned arrived = atomicAdd(&g_bar_cnt, 1u);
        if (arrived == NCTA - 1) {
            atomicExch(&g_bar_cnt, 0u);
            __threadfence();
            atomicAdd(&g_bar_phase, 1u);
        } else {
            volatile unsigned* vp = &g_bar_phase;
            while ((int)(*vp - target) < 0)
                __nanosleep(32);
            __threadfence();
        }
    }
    __syncthreads();
}

__global__ void __launch_bounds__(256, 1)
rnn_persistent_kernel(const float* __restrict__ xp_enc,
                      const float* __restrict__ xp_dec,
                      const float* __restrict__ enc_Whh,
                      const float* __restrict__ dec_Whh,
                      float* __restrict__ states,
                      float* __restrict__ hT0,
                      float* __restrict__ hT1)
{
    extern __shared__ float sm[];
    float* Ws = sm;                       // [1024][36]
    float* hs = sm + WS_F;                // 2 x [128 k][32 b]
    unsigned long long* pbuf = reinterpret_cast<unsigned long long*>(hs); // reduction reuse

    const int tid = threadIdx.x;
    const int ni = blockIdx.x, mi = blockIdx.y;
    const int btile = mi * 32, ntile = ni * 32;

    const int ksg = tid >> 6;             // 0..3 : k-interleave group
    const int gt  = tid & 63;
    const int b_local = (gt & 7) * 4;     // 4 batch rows
    const int n_local = (gt >> 3) * 4;    // 4 hidden cols

    // Staging decomposition (all 256 threads): fixed col, 4 k-rows.
    const int s_kl  = tid >> 3;           // base k row (0..31), +32 per i
    const int s_col = (tid & 7) * 4;      // b column

    __shared__ unsigned s_ph;
    if (tid == 0) s_ph = *(volatile unsigned*)&g_bar_phase;

    // Zero h0 (ping): 128 CTAs x 256 threads x 4 floats = 131072.
    {
        const int cta = mi * 32 + ni;
        *reinterpret_cast<float4*>(&hT0[(cta * 256 + tid) * 4]) =
            make_float4(0.f, 0.f, 0.f, 0.f);
    }

    load_whh_slice(Ws, enc_Whh, ntile, tid);
    __syncthreads();
    unsigned target = s_ph + 1;
    grid_barrier(target);

    for (int s = 0; s < 512; s++) {
        if (s == 256) {
            load_whh_slice(Ws, dec_Whh, ntile, tid);
            __syncthreads();
        }
        const float* __restrict__ hin  = (s & 1) ? hT1 : hT0;
        float* __restrict__       hout = (s & 1) ? hT0 : hT1;
        const int t = s & 255;
        const float* __restrict__ xp = (s < 256) ? xp_enc : xp_dec;

        // Epilogue xp prefetch (ksg0 threads only; hidden under the GEMM).
        float4 xr[4];
        if (ksg == 0) {
            #pragma unroll
            for (int b = 0; b < 4; b++)
                xr[b] = *reinterpret_cast<const float4*>(
                    &xp[((size_t)(btile + b_local + b) * MAXLEN + t) * DHID + ntile + n_local]);
        }

        // Stage chunk 0.
        float4 r[4];
        #pragma unroll
        for (int i = 0; i < 4; i++)
            r[i] = *reinterpret_cast<const float4*>(
                &hin[(s_kl + i * 32) * BSZ + btile + s_col]);
        #pragma unroll
        for (int i = 0; i < 4; i++)
            *reinterpret_cast<float4*>(&hs[(s_kl + i * 32) * 32 + s_col]) = r[i];
        __syncthreads();

        unsigned long long acc[4][2] = {};   // [b][n-pair]

        #pragma unroll 1
        for (int c = 0; c < 8; c++) {
            const int cb = c & 1;
            if (c < 7) {
                #pragma unroll
                for (int i = 0; i < 4; i++)
                    r[i] = *reinterpret_cast<const float4*>(
                        &hin[((c + 1) * KC + s_kl + i * 32) * BSZ + btile + s_col]);
            }
            const float* hp = hs + cb * CHUNK_F + b_local;
            const float* wp = Ws + (c * KC + ksg) * WS_STRIDE + n_local;
            #pragma unroll 8
            for (int i = 0; i < 32; i++) {
                float4 h4 = *reinterpret_cast<const float4*>(hp + (i * 4 + ksg) * 32);
                ulonglong2 w2 = *reinterpret_cast<const ulonglong2*>(wp + i * 4 * WS_STRIDE);
                unsigned long long d0 = dupf(h4.x), d1 = dupf(h4.y);
                unsigned long long d2 = dupf(h4.z), d3 = dupf(h4.w);
                ffma2(acc[0][0], d0, w2.x); ffma2(acc[0][1], d0, w2.y);
                ffma2(acc[1][0], d1, w2.x); ffma2(acc[1][1], d1, w2.y);
                ffma2(acc[2][0], d2, w2.x); ffma2(acc[2][1], d2, w2.y);
                ffma2(acc[3][0], d3, w2.x); ffma2(acc[3][1], d3, w2.y);
            }
            if (c < 7) {
                #pragma unroll
                for (int i = 0; i < 4; i++)
                    *reinterpret_cast<float4*>(
                        &hs[(1 - cb) * CHUNK_F + (s_kl + i * 32) * 32 + s_col]) = r[i];
                __syncthreads();
            }
        }

        // Split-k reduction: groups 1..3 park partials in smem (chunks now idle).
        __syncthreads();
        if (ksg > 0) {
            unsigned long long* dst = pbuf + ((size_t)((ksg - 1) * 64 + gt)) * 9;
            #pragma unroll
            for (int b = 0; b < 4; b++) {
                dst[b * 2 + 0] = acc[b][0];
                dst[b * 2 + 1] = acc[b][1];
            }
        }
        __syncthreads();

        if (ksg == 0) {
            #pragma unroll
            for (int j = 0; j < 3; j++) {
                const unsigned long long* src = pbuf + ((size_t)(j * 64 + gt)) * 9;
                #pragma unroll
                for (int b = 0; b < 4; b++) {
                    add2(acc[b][0], src[b * 2 + 0]);
                    add2(acc[b][1], src[b * 2 + 1]);
                }
            }

            float th[4][4];
            #pragma unroll
            for (int b = 0; b < 4; b++) {
                float2 v0 = u64_to_f2(acc[b][0]);
                float2 v1 = u64_to_f2(acc[b][1]);
                th[b][0] = tanhf(v0.x + xr[b].x);
                th[b][1] = tanhf(v0.y + xr[b].y);
                th[b][2] = tanhf(v1.x + xr[b].z);
                th[b][3] = tanhf(v1.y + xr[b].w);
            }

            #pragma unroll
            for (int nj = 0; nj < 4; nj++)
                *reinterpret_cast<float4*>(
                    &hout[(ntile + n_local + nj) * BSZ + btile + b_local]) =
                    make_float4(th[0][nj], th[1][nj], th[2][nj], th[3][nj]);

            if (s >= 256) {
                #pragma unroll
                for (int b = 0; b < 4; b++)
                    *reinterpret_cast<float4*>(
                        &states[((size_t)(btile + b_local + b) * MAXLEN + t) * DHID +
                                ntile + n_local]) =
                        make_float4(th[b][0], th[b][1], th[b][2], th[b][3]);
            }
        }

        target++;
        grid_barrier(target);
    }
}

// ---------------------------------------------------------------------------
// In-place row-wise log-softmax over VOC=512 columns. One warp per row.
// ---------------------------------------------------------------------------
__global__ void log_softmax_kernel(float* __restrict__ data)
{
    int gw   = (blockIdx.x * blockDim.x + threadIdx.x) >> 5;
    int lane = threadIdx.x & 31;
    if (gw >= BT) return;
    float* row = data + (size_t)gw * VOC;

    float v[16];
    float mx = -1e30f;
    #pragma unroll
    for (int i = 0; i < 16; i++) {
        v[i] = row[lane + i * 32];
        mx = fmaxf(mx, v[i]);
    }
    #pragma unroll
    for (int o = 16; o > 0; o >>= 1)
        mx = fmaxf(mx, __shfl_xor_sync(0xffffffffu, mx, o));

    float s = 0.0f;
    #pragma unroll
    for (int i = 0; i < 16; i++) s += expf(v[i] - mx);
    #pragma unroll
    for (int o = 16; o > 0; o >>= 1)
        s += __shfl_xor_sync(0xffffffffu, s, o);

    float lse = mx + logf(s);
    #pragma unroll
    for (int i = 0; i < 16; i++) row[lane + i * 32] = v[i] - lse;
}

// ---------------------------------------------------------------------------
extern "C" void kernel_launch(void* const* d_in, const int* in_sizes, int n_in,
                              void* d_out, int out_size)
{
    const int*   inputs  = (const int*)d_in[0];
    const int*   outputs = (const int*)d_in[1];
    const float* emb     = (const float*)d_in[2];
    const float* enc_Wih = (const float*)d_in[3];
    const float* enc_Whh = (const float*)d_in[4];
    const float* enc_bih = (const float*)d_in[5];
    const float* enc_bhh = (const float*)d_in[6];
    const float* dec_Wih = (const float*)d_in[7];
    const float* dec_Whh = (const float*)d_in[8];
    const float* dec_bih = (const float*)d_in[9];
    const float* dec_bhh = (const float*)d_in[10];
    const float* out_W   = (const float*)d_in[11];
    const float* out_b   = (const float*)d_in[12];
    float* out = (float*)d_out;

    float *xp_enc, *xp_dec, *states, *hT0, *hT1;
    cudaGetSymbolAddress((void**)&xp_enc, g_xp_enc);
    cudaGetSymbolAddress((void**)&xp_dec, g_xp_dec);
    cudaGetSymbolAddress((void**)&states, g_states);
    cudaGetSymbolAddress((void**)&hT0,    g_hT0);
    cudaGetSymbolAddress((void**)&hT1,    g_hT1);

    // Input projections (embedding gather fused): xp = emb[tok] @ Wih^T + bih + bhh
    gemm_gather_kernel<<<dim3(DHID / GBN, BT / GBM), 256>>>(
        emb, DCHAR, inputs, 1, MAXLEN, enc_Wih, enc_bih, enc_bhh, xp_enc, DHID, DCHAR);
    gemm_gather_kernel<<<dim3(DHID / GBN, BT / GBM), 256>>>(
        emb, DCHAR, outputs, 2, MAXLEN, dec_Wih, dec_bih, dec_bhh, xp_dec, DHID, DCHAR);

    // Persistent recurrence: encoder 256 steps + decoder 256 steps, grid-synced.
    cudaFuncSetAttribute(rnn_persistent_kernel,
                         cudaFuncAttributeMaxDynamicSharedMemorySize, SMEM_BYTES);
    rnn_persistent_kernel<<<dim3(32, 4), 256, SMEM_BYTES>>>(
        xp_enc, xp_dec, enc_Whh, dec_Whh, states, hT0, hT1);

    // logits = states @ out_W^T + out_b -> d_out, then log-softmax in place.
    gemm_gather_kernel<<<dim3(VOC / GBN, BT / GBM), 256>>>(
        states, DHID, nullptr, 0, MAXLEN, out_W, out_b, nullptr, out, VOC, DHID);

    log_softmax_kernel<<<BT / 8, 256>>>(out);
}

// round 7
// speedup vs baseline: 1.7311x; 1.3038x over previous
#include <cuda_runtime.h>
#include <math.h>

#define BSZ    128
#define MAXLEN 256
#define DCHAR  256
#define DHID   1024
#define VOC    512
#define BT     (BSZ * MAXLEN)   // 32768
#define BH     (BSZ * DHID)     // 131072

// ---------------------------------------------------------------------------
// Scratch (allocation-free: __device__ globals)
// ---------------------------------------------------------------------------
__device__ float g_xp_enc[BT * DHID];
__device__ float g_xp_dec[BT * DHID];
__device__ float g_states[BT * DHID];
__device__ float g_hT0[DHID * BSZ];     // transposed hidden ping [k][b]
__device__ float g_hT1[DHID * BSZ];     // transposed hidden pong [k][b]

// Per-row-group barriers (4 groups of 32 CTAs), 128B apart to avoid L2-line sharing.
__device__ unsigned g_bar_cnt[4 * 32];
__device__ unsigned g_bar_phase[4 * 32];

// ---------------------------------------------------------------------------
// f32x2 helpers
// ---------------------------------------------------------------------------
__device__ __forceinline__ unsigned long long dupf(float x)
{
    unsigned long long r;
    asm("mov.b64 %0,{%1,%1};" : "=l"(r) : "f"(x));
    return r;
}
__device__ __forceinline__ void ffma2(unsigned long long& a,
                                      unsigned long long x, unsigned long long y)
{
    asm("fma.rn.f32x2 %0,%1,%2,%0;" : "+l"(a) : "l"(x), "l"(y));
}
__device__ __forceinline__ void add2(unsigned long long& a, unsigned long long x)
{
    asm("add.rn.f32x2 %0,%0,%1;" : "+l"(a) : "l"(x));
}
__device__ __forceinline__ float2 u64_to_f2(unsigned long long v)
{
    float2 f;
    asm("mov.b64 {%0,%1},%2;" : "=f"(f.x), "=f"(f.y) : "l"(v));
    return f;
}

// ---------------------------------------------------------------------------
// Tiled SGEMM with row gather, v5: plain (non-duplicated) smem staging like R4,
// FFMA2 inner loop with REGISTER duplication of B (1 MOV each, no smem dup).
// Per k per thread: LDS.64 (A m-pair x2) + LDS.128 (B) + 4 MOV + 8 FFMA2
//   = 14 issue slots / 16 MAC; FMA pipe 16 cyc vs 32 scalar -> FMA-bound at 2x.
//   C[row, n] = sum_k A[src(row), k] * B[n, k] + bias1[n] (+ bias2[n])
// ---------------------------------------------------------------------------
#define GBM 64
#define GBN 64
#define GBK 16

__global__ void gemm_gather_kernel(const float* __restrict__ A, int lda,
                                   const int* __restrict__ tokens, int gmode, int T,
                                   const float* __restrict__ B,
                                   const float* __restrict__ bias1,
                                   const float* __restrict__ bias2,
                                   float* __restrict__ C,
                                   int N, int K)
{
    __shared__ __align__(16) float As[GBK][GBM + 4];
    __shared__ __align__(16) float Bs[GBK][GBN + 4];
    __shared__ int rowsrc[GBM];

    const int bm  = blockIdx.y * GBM;
    const int bn  = blockIdx.x * GBN;
    const int tid = threadIdx.x;

    if (tid < GBM) {
        int row = bm + tid;
        int src = row;
        if (gmode == 1) {
            src = tokens[row];
        } else if (gmode == 2) {
            int t = row % T;
            src = (t == 0) ? -1 : tokens[row - 1];
        }
        rowsrc[tid] = src;
    }
    __syncthreads();

    const int tm = (tid >> 4) * 4;
    const int tn = (tid & 15) * 4;

    unsigned long long acc2[2][4] = {};   // [m-pair][n]

    for (int k0 = 0; k0 < K; k0 += GBK) {
        #pragma unroll
        for (int i = 0; i < 4; i++) {
            int idx = tid + i * 256;
            int m = idx >> 4, kk = idx & 15;
            int src = rowsrc[m];
            As[kk][m] = (src < 0) ? 0.0f : A[src * lda + k0 + kk];
        }
        #pragma unroll
        for (int i = 0; i < 4; i++) {
            int idx = tid + i * 256;
            int n = idx >> 4, kk = idx & 15;
            Bs[kk][n] = B[(bn + n) * K + k0 + kk];
        }
        __syncthreads();

        #pragma unroll
        for (int kk = 0; kk < GBK; kk++) {
            unsigned long long a01 =
                *reinterpret_cast<const unsigned long long*>(&As[kk][tm]);
            unsigned long long a23 =
                *reinterpret_cast<const unsigned long long*>(&As[kk][tm + 2]);
            float4 b4 = *reinterpret_cast<const float4*>(&Bs[kk][tn]);
            unsigned long long b0 = dupf(b4.x), b1 = dupf(b4.y);
            unsigned long long b2 = dupf(b4.z), b3 = dupf(b4.w);
            ffma2(acc2[0][0], a01, b0);
            ffma2(acc2[0][1], a01, b1);
            ffma2(acc2[0][2], a01, b2);
            ffma2(acc2[0][3], a01, b3);
            ffma2(acc2[1][0], a23, b0);
            ffma2(acc2[1][1], a23, b1);
            ffma2(acc2[1][2], a23, b2);
            ffma2(acc2[1][3], a23, b3);
        }
        __syncthreads();
    }

    #pragma unroll
    for (int j = 0; j < 4; j++) {
        int n = bn + tn + j;
        float bb = (bias1 ? bias1[n] : 0.0f) + (bias2 ? bias2[n] : 0.0f);
        float2 p0 = u64_to_f2(acc2[0][j]);
        float2 p1 = u64_to_f2(acc2[1][j]);
        C[(bm + tm + 0) * N + n] = p0.x + bb;
        C[(bm + tm + 1) * N + n] = p0.y + bb;
        C[(bm + tm + 2) * N + n] = p1.x + bb;
        C[(bm + tm + 3) * N + n] = p1.y + bb;
    }
}

// ---------------------------------------------------------------------------
// Persistent recurrence kernel, v4 = v3 core + split row-group barriers.
// 128 CTAs (1/SM), 256 threads. CTA (ni, mi) owns b in [32*mi,+32), n in [32*ni,+32).
// Step s+1 of CTA (mi, *) depends ONLY on step-s writes of CTAs sharing mi,
// so each mi-group of 32 CTAs syncs independently.
// ---------------------------------------------------------------------------
#define NGRP_CTA  32
#define WS_STRIDE 36
#define WS_F      (DHID * WS_STRIDE)    // 36864 floats (144 KB)
#define KC        128                   // staged k-chunk
#define CHUNK_F   (KC * 32)             // 4096 floats (16 KB)
#define SMEM_BYTES ((WS_F + 2 * CHUNK_F) * 4)   // 180224 B

__device__ __forceinline__ void load_whh_slice(float* Ws, const float* __restrict__ W,
                                               int ntile, int tid)
{
    for (int idx = tid; idx < 32 * 256; idx += 256) {
        int row = idx >> 8;          // 0..31 (n local)
        int c4  = idx & 255;         // 0..255 (k/4)
        float4 v = *reinterpret_cast<const float4*>(&W[(ntile + row) * DHID + c4 * 4]);
        int k = c4 * 4;
        Ws[(k + 0) * WS_STRIDE + row] = v.x;
        Ws[(k + 1) * WS_STRIDE + row] = v.y;
        Ws[(k + 2) * WS_STRIDE + row] = v.z;
        Ws[(k + 3) * WS_STRIDE + row] = v.w;
    }
}

__device__ __forceinline__ void group_barrier(int grp, unsigned target)
{
    __syncthreads();
    if (threadIdx.x == 0) {
        unsigned* cnt = &g_bar_cnt[grp * 32];
        unsigned* ph  = &g_bar_phase[grp * 32];
        __threadfence();
        unsigned arrived = atomicAdd(cnt, 1u);
        if (arrived == NGRP_CTA - 1) {
            atomicExch(cnt, 0u);
            __threadfence();
            atomicAdd(ph, 1u);
        } else {
            volatile unsigned* vp = ph;
            while ((int)(*vp - target) < 0)
                __nanosleep(20);
            __threadfence();
        }
    }
    __syncthreads();
}

__global__ void __launch_bounds__(256, 1)
rnn_persistent_kernel(const float* __restrict__ xp_enc,
                      const float* __restrict__ xp_dec,
                      const float* __restrict__ enc_Whh,
                      const float* __restrict__ dec_Whh,
                      float* __restrict__ states,
                      float* __restrict__ hT0,
                      float* __restrict__ hT1)
{
    extern __shared__ float sm[];
    float* Ws = sm;                       // [1024][36]
    float* hs = sm + WS_F;                // 2 x [128 k][32 b]
    unsigned long long* pbuf = reinterpret_cast<unsigned long long*>(hs);

    const int tid = threadIdx.x;
    const int ni = blockIdx.x, mi = blockIdx.y;
    const int btile = mi * 32, ntile = ni * 32;

    const int ksg = tid >> 6;             // 0..3 : k-interleave group
    const int gt  = tid & 63;
    const int b_local = (gt & 7) * 4;     // 4 batch rows
    const int n_local = (gt >> 3) * 4;    // 4 hidden cols

    const int s_kl  = tid >> 3;           // staging: base k row, +32 per i
    const int s_col = (tid & 7) * 4;      // staging: b column

    __shared__ unsigned s_ph;
    if (tid == 0) s_ph = *(volatile unsigned*)&g_bar_phase[mi * 32];

    // Zero this group's slice of h0: k in [ni*32,+32), b in [btile,+32).
    #pragma unroll
    for (int i = 0; i < 4; i++) {
        int idx = tid + i * 256;           // 0..1023 = 32k x 8 col-quads
        int k = ni * 32 + (idx >> 3);
        int col = (idx & 7) * 4;
        *reinterpret_cast<float4*>(&hT0[k * BSZ + btile + col]) =
            make_float4(0.f, 0.f, 0.f, 0.f);
    }

    load_whh_slice(Ws, enc_Whh, ntile, tid);
    __syncthreads();
    unsigned target = s_ph + 1;
    group_barrier(mi, target);

    for (int s = 0; s < 512; s++) {
        if (s == 256) {
            load_whh_slice(Ws, dec_Whh, ntile, tid);
            __syncthreads();
        }
        const float* __restrict__ hin  = (s & 1) ? hT1 : hT0;
        float* __restrict__       hout = (s & 1) ? hT0 : hT1;
        const int t = s & 255;
        const float* __restrict__ xp = (s < 256) ? xp_enc : xp_dec;

        // Epilogue xp prefetch (ksg0 threads only; hidden under the GEMM).
        float4 xr[4];
        if (ksg == 0) {
            #pragma unroll
            for (int b = 0; b < 4; b++)
                xr[b] = *reinterpret_cast<const float4*>(
                    &xp[((size_t)(btile + b_local + b) * MAXLEN + t) * DHID + ntile + n_local]);
        }

        // Stage chunk 0.
        float4 r[4];
        #pragma unroll
        for (int i = 0; i < 4; i++)
            r[i] = *reinterpret_cast<const float4*>(
                &hin[(s_kl + i * 32) * BSZ + btile + s_col]);
        #pragma unroll
        for (int i = 0; i < 4; i++)
            *reinterpret_cast<float4*>(&hs[(s_kl + i * 32) * 32 + s_col]) = r[i];
        __syncthreads();

        unsigned long long acc[4][2] = {};   // [b][n-pair]

        #pragma unroll 1
        for (int c = 0; c < 8; c++) {
            const int cb = c & 1;
            if (c < 7) {
                #pragma unroll
                for (int i = 0; i < 4; i++)
                    r[i] = *reinterpret_cast<const float4*>(
                        &hin[((c + 1) * KC + s_kl + i * 32) * BSZ + btile + s_col]);
            }
            const float* hp = hs + cb * CHUNK_F + b_local;
            const float* wp = Ws + (c * KC + ksg) * WS_STRIDE + n_local;
            #pragma unroll 8
            for (int i = 0; i < 32; i++) {
                float4 h4 = *reinterpret_cast<const float4*>(hp + (i * 4 + ksg) * 32);
                ulonglong2 w2 = *reinterpret_cast<const ulonglong2*>(wp + i * 4 * WS_STRIDE);
                unsigned long long d0 = dupf(h4.x), d1 = dupf(h4.y);
                unsigned long long d2 = dupf(h4.z), d3 = dupf(h4.w);
                ffma2(acc[0][0], d0, w2.x); ffma2(acc[0][1], d0, w2.y);
                ffma2(acc[1][0], d1, w2.x); ffma2(acc[1][1], d1, w2.y);
                ffma2(acc[2][0], d2, w2.x); ffma2(acc[2][1], d2, w2.y);
                ffma2(acc[3][0], d3, w2.x); ffma2(acc[3][1], d3, w2.y);
            }
            if (c < 7) {
                #pragma unroll
                for (int i = 0; i < 4; i++)
                    *reinterpret_cast<float4*>(
                        &hs[(1 - cb) * CHUNK_F + (s_kl + i * 32) * 32 + s_col]) = r[i];
                __syncthreads();
            }
        }

        // Split-k reduction: groups 1..3 park partials in smem (chunks now idle).
        __syncthreads();
        if (ksg > 0) {
            unsigned long long* dst = pbuf + ((size_t)((ksg - 1) * 64 + gt)) * 9;
            #pragma unroll
            for (int b = 0; b < 4; b++) {
                dst[b * 2 + 0] = acc[b][0];
                dst[b * 2 + 1] = acc[b][1];
            }
        }
        __syncthreads();

        if (ksg == 0) {
            #pragma unroll
            for (int j = 0; j < 3; j++) {
                const unsigned long long* src = pbuf + ((size_t)(j * 64 + gt)) * 9;
                #pragma unroll
                for (int b = 0; b < 4; b++) {
                    add2(acc[b][0], src[b * 2 + 0]);
                    add2(acc[b][1], src[b * 2 + 1]);
                }
            }

            float th[4][4];
            #pragma unroll
            for (int b = 0; b < 4; b++) {
                float2 v0 = u64_to_f2(acc[b][0]);
                float2 v1 = u64_to_f2(acc[b][1]);
                th[b][0] = tanhf(v0.x + xr[b].x);
                th[b][1] = tanhf(v0.y + xr[b].y);
                th[b][2] = tanhf(v1.x + xr[b].z);
                th[b][3] = tanhf(v1.y + xr[b].w);
            }

            #pragma unroll
            for (int nj = 0; nj < 4; nj++)
                *reinterpret_cast<float4*>(
                    &hout[(ntile + n_local + nj) * BSZ + btile + b_local]) =
                    make_float4(th[0][nj], th[1][nj], th[2][nj], th[3][nj]);

            if (s >= 256) {
                #pragma unroll
                for (int b = 0; b < 4; b++)
                    *reinterpret_cast<float4*>(
                        &states[((size_t)(btile + b_local + b) * MAXLEN + t) * DHID +
                                ntile + n_local]) =
                        make_float4(th[b][0], th[b][1], th[b][2], th[b][3]);
            }
        }

        target++;
        group_barrier(mi, target);
    }
}

// ---------------------------------------------------------------------------
// No-op pad kernel: shifts the persistent kernel to ncu's -s 5 capture slot.
// ---------------------------------------------------------------------------
__global__ void noop_kernel() {}

// ---------------------------------------------------------------------------
// In-place row-wise log-softmax over VOC=512 columns. One warp per row.
// ---------------------------------------------------------------------------
__global__ void log_softmax_kernel(float* __restrict__ data)
{
    int gw   = (blockIdx.x * blockDim.x + threadIdx.x) >> 5;
    int lane = threadIdx.x & 31;
    if (gw >= BT) return;
    float* row = data + (size_t)gw * VOC;

    float v[16];
    float mx = -1e30f;
    #pragma unroll
    for (int i = 0; i < 16; i++) {
        v[i] = row[lane + i * 32];
        mx = fmaxf(mx, v[i]);
    }
    #pragma unroll
    for (int o = 16; o > 0; o >>= 1)
        mx = fmaxf(mx, __shfl_xor_sync(0xffffffffu, mx, o));

    float s = 0.0f;
    #pragma unroll
    for (int i = 0; i < 16; i++) s += expf(v[i] - mx);
    #pragma unroll
    for (int o = 16; o > 0; o >>= 1)
        s += __shfl_xor_sync(0xffffffffu, s, o);

    float lse = mx + logf(s);
    #pragma unroll
    for (int i = 0; i < 16; i++) row[lane + i * 32] = v[i] - lse;
}

// ---------------------------------------------------------------------------
extern "C" void kernel_launch(void* const* d_in, const int* in_sizes, int n_in,
                              void* d_out, int out_size)
{
    const int*   inputs  = (const int*)d_in[0];
    const int*   outputs = (const int*)d_in[1];
    const float* emb     = (const float*)d_in[2];
    const float* enc_Wih = (const float*)d_in[3];
    const float* enc_Whh = (const float*)d_in[4];
    const float* enc_bih = (const float*)d_in[5];
    const float* enc_bhh = (const float*)d_in[6];
    const float* dec_Wih = (const float*)d_in[7];
    const float* dec_Whh = (const float*)d_in[8];
    const float* dec_bih = (const float*)d_in[9];
    const float* dec_bhh = (const float*)d_in[10];
    const float* out_W   = (const float*)d_in[11];
    const float* out_b   = (const float*)d_in[12];
    float* out = (float*)d_out;

    float *xp_enc, *xp_dec, *states, *hT0, *hT1;
    cudaGetSymbolAddress((void**)&xp_enc, g_xp_enc);
    cudaGetSymbolAddress((void**)&xp_dec, g_xp_dec);
    cudaGetSymbolAddress((void**)&states, g_states);
    cudaGetSymbolAddress((void**)&hT0,    g_hT0);
    cudaGetSymbolAddress((void**)&hT1,    g_hT1);

    // Input projections (embedding gather fused): xp = emb[tok] @ Wih^T + bih + bhh
    gemm_gather_kernel<<<dim3(DHID / GBN, BT / GBM), 256>>>(
        emb, DCHAR, inputs, 1, MAXLEN, enc_Wih, enc_bih, enc_bhh, xp_enc, DHID, DCHAR);
    gemm_gather_kernel<<<dim3(DHID / GBN, BT / GBM), 256>>>(
        emb, DCHAR, outputs, 2, MAXLEN, dec_Wih, dec_bih, dec_bhh, xp_dec, DHID, DCHAR);

    // Pads: make the persistent kernel the 6th launch (ncu -s 5 -c 1 capture slot).
    noop_kernel<<<1, 32>>>();
    noop_kernel<<<1, 32>>>();
    noop_kernel<<<1, 32>>>();

    // Persistent recurrence: encoder 256 steps + decoder 256 steps, row-group-synced.
    cudaFuncSetAttribute(rnn_persistent_kernel,
                         cudaFuncAttributeMaxDynamicSharedMemorySize, SMEM_BYTES);
    rnn_persistent_kernel<<<dim3(32, 4), 256, SMEM_BYTES>>>(
        xp_enc, xp_dec, enc_Whh, dec_Whh, states, hT0, hT1);

    // logits = states @ out_W^T + out_b -> d_out, then log-softmax in place.
    gemm_gather_kernel<<<dim3(VOC / GBN, BT / GBM), 256>>>(
        states, DHID, nullptr, 0, MAXLEN, out_W, out_b, nullptr, out, VOC, DHID);

    log_softmax_kernel<<<BT / 8, 256>>>(out);
}